// round 17
// baseline (speedup 1.0000x reference)
#include <cuda_runtime.h>

// Problem constants (fixed shapes from reference):
//   x : (2, 128, 96, 96) f32, w{q,k,v} : (4, 32, 32) f32
//   K = 5 window, reflect pad 2, G = 4 groups of 32 channels.
#define BB   2
#define GG   4
#define CIN  32
#define CON  32
#define HHN  96
#define WWN  96
#define HWSZ (HHN * WWN)
#define CTOT 128

// Scratch for the three 1x1-conv outputs (q, k, v), each (B, 128, 96, 96).
// g_q holds q PRE-SCALED by log2(e) (folded into wq at weight staging).
__device__ __align__(256) float g_q[BB * CTOT * HWSZ];
__device__ __align__(256) float g_k[BB * CTOT * HWSZ];
__device__ __align__(256) float g_v[BB * CTOT * HWSZ];

// -----------------------------------------------------------------------------
// Kernel A: grouped 1x1 convs (q, k, v) fused — one CTA per (b, g, h) row.
// R10 mainloop config (best measured): scalar FFMA, float4 x staging,
// __launch_bounds__(256,2), direct stores. This round targets the EXPOSED
// PROLOGUE (the mainloop is fma-pipe-bound; issue tweaks there were measured
// neutral): weights now stage with 3 LDG.128 + 3 STS.128 per thread (stride
// 36 keeps 16B alignment) instead of 12 scalar LDG + 12 scalar STS, and the
// mainloop reads them as one LDS.128 per 4 i-steps.
// Ledger of regressions: plain bounds (20.0), f32x2 (19.4), smem-bounce
// epilogue (19.5), small-tile split (22.3), chunked launches (49.7 total),
// full fusion (57.8 total). Do not restructure.
// -----------------------------------------------------------------------------
#define WSTR 36   // weight smem row stride (floats); o*36*4B = o*144B, 16B-aligned

__global__ __launch_bounds__(256, 2) void qkv_kernel(
    const float* __restrict__ x,
    const float* __restrict__ wq,
    const float* __restrict__ wk,
    const float* __restrict__ wv)
{
    __shared__ float xs[CIN * WWN];                       // 12 KB
    __shared__ __align__(16) float wqs[CON * WSTR];       // 4.6 KB each
    __shared__ __align__(16) float wks[CON * WSTR];
    __shared__ __align__(16) float wvs[CON * WSTR];

    const int h   = blockIdx.x;
    const int bg  = blockIdx.y;                // b*G + g
    const int g   = bg & (GG - 1);
    const int tid = threadIdx.x;

    // Stage x row with float4 loads: x[bg*32 + i][h][w]
    const float* xbase = x + (size_t)bg * CIN * HWSZ + (size_t)h * WWN;
    #pragma unroll
    for (int idx = tid; idx < CIN * (WWN / 4); idx += 256) {
        int i  = idx / (WWN / 4);
        int w4 = idx - i * (WWN / 4);
        reinterpret_cast<float4*>(xs)[i * (WWN / 4) + w4] =
            reinterpret_cast<const float4*>(xbase + (size_t)i * HWSZ)[w4];
    }
    // Stage weights of this group, vectorized: exactly one (o, i4) per thread.
    // wq is pre-scaled by log2(e) so attn feeds q straight into ex2.
    {
        const float L2E = 1.44269504088896341f;
        const float* wqg = wq + (size_t)g * CON * CIN;
        const float* wkg = wk + (size_t)g * CON * CIN;
        const float* wvg = wv + (size_t)g * CON * CIN;
        int o  = tid >> 3;                     // 0..31
        int i4 = (tid & 7) * 4;                // 0,4,...,28
        float4 a = *reinterpret_cast<const float4*>(wqg + o * 32 + i4);
        float4 b = *reinterpret_cast<const float4*>(wkg + o * 32 + i4);
        float4 c = *reinterpret_cast<const float4*>(wvg + o * 32 + i4);
        *reinterpret_cast<float4*>(&wqs[o * WSTR + i4]) =
            make_float4(a.x * L2E, a.y * L2E, a.z * L2E, a.w * L2E);
        *reinterpret_cast<float4*>(&wks[o * WSTR + i4]) = b;
        *reinterpret_cast<float4*>(&wvs[o * WSTR + i4]) = c;
    }
    __syncthreads();

    const int o    = tid >> 3;            // 0..31 output channel
    const int wseg = (tid & 7) * 12;      // 12 consecutive w positions

    float aq[12], ak[12], av[12];
    #pragma unroll
    for (int u = 0; u < 12; u++) { aq[u] = 0.f; ak[u] = 0.f; av[u] = 0.f; }

    #pragma unroll
    for (int i0 = 0; i0 < CIN; i0 += 4) {
        const float4 wq4 = *reinterpret_cast<const float4*>(&wqs[o * WSTR + i0]);
        const float4 wk4 = *reinterpret_cast<const float4*>(&wks[o * WSTR + i0]);
        const float4 wv4 = *reinterpret_cast<const float4*>(&wvs[o * WSTR + i0]);
        const float wqa[4] = { wq4.x, wq4.y, wq4.z, wq4.w };
        const float wka[4] = { wk4.x, wk4.y, wk4.z, wk4.w };
        const float wva[4] = { wv4.x, wv4.y, wv4.z, wv4.w };
        #pragma unroll
        for (int j = 0; j < 4; j++) {
            const float4* xv = reinterpret_cast<const float4*>(&xs[(i0 + j) * WWN + wseg]);
            float4 x0 = xv[0], x1 = xv[1], x2 = xv[2];
            float xr[12] = { x0.x, x0.y, x0.z, x0.w,
                             x1.x, x1.y, x1.z, x1.w,
                             x2.x, x2.y, x2.z, x2.w };
            #pragma unroll
            for (int u = 0; u < 12; u++) {
                aq[u] = fmaf(xr[u], wqa[j], aq[u]);
                ak[u] = fmaf(xr[u], wka[j], ak[u]);
                av[u] = fmaf(xr[u], wva[j], av[u]);
            }
        }
    }

    const size_t obase = (size_t)(bg * CON + o) * HWSZ + (size_t)h * WWN + wseg;
    float4* qo = reinterpret_cast<float4*>(&g_q[obase]);
    float4* ko = reinterpret_cast<float4*>(&g_k[obase]);
    float4* vo = reinterpret_cast<float4*>(&g_v[obase]);
    #pragma unroll
    for (int u = 0; u < 3; u++) {
        qo[u] = make_float4(aq[4*u], aq[4*u+1], aq[4*u+2], aq[4*u+3]);
        ko[u] = make_float4(ak[4*u], ak[4*u+1], ak[4*u+2], ak[4*u+3]);
        vo[u] = make_float4(av[4*u], av[4*u+1], av[4*u+2], av[4*u+3]);
    }
}

// -----------------------------------------------------------------------------
// Kernel B: per-channel 5x5 windowed softmax with reflect indexing.
// VERBATIM R16 (best measured attn, 16.3us): 256 threads (8 tx x 32 ty),
// 4 consecutive w outputs/thread, LDS.128 halo stride 44, q pre-scaled by
// log2(e), q4 load hoisted above halo staging, pure-MUFU single-pass softmax.
// Ledger of regressions: 128-thread/8-output tiles (21.0), hybrid poly-exp
// (19.9), chunked launches, fused single kernel.
// -----------------------------------------------------------------------------
__device__ __forceinline__ int refl(int i, int n) {
    return i < 0 ? -i : (i >= n ? 2 * n - 2 - i : i);
}

__device__ __forceinline__ float ex2(float x) {
    float y;
    asm("ex2.approx.ftz.f32 %0, %1;" : "=f"(y) : "f"(x));
    return y;
}

#define HALO 36
#define HSTR 44

__global__ __launch_bounds__(256) void attn_kernel(float* __restrict__ out)
{
    __shared__ __align__(16) float ks[HALO * HSTR];   // 6.3 KB
    __shared__ __align__(16) float vs[HALO * HSTR];

    const int ch  = blockIdx.z;               // 0..255 = b*128 + channel
    const int h0  = blockIdx.y * 32;
    const int w0  = blockIdx.x * 32;
    const int tid = threadIdx.x;
    const int tx  = tid & 7;                  // 8 threads across w (4 outputs each)
    const int ty  = tid >> 3;                 // 32 rows

    const size_t cbase = (size_t)ch * HWSZ;
    const int h    = h0 + ty;
    const int wsub = tx * 4;                  // halo column base for this thread
    const size_t pix = (size_t)h * WWN + (w0 + wsub);

    // Hoisted q load (already scaled by log2 e in qkv) — overlaps staging.
    const float4 q4 = *reinterpret_cast<const float4*>(&g_q[cbase + pix]);

    // Stage k/v halos (36x36 window, reflect at global borders).
    #pragma unroll
    for (int idx = tid; idx < HALO * HALO; idx += 256) {
        int r  = idx / HALO;
        int c  = idx - r * HALO;
        int hh = refl(h0 - 2 + r, HHN);
        int ww = refl(w0 - 2 + c, WWN);
        size_t gi = cbase + (size_t)hh * WWN + ww;
        ks[r * HSTR + c] = g_k[gi];
        vs[r * HSTR + c] = g_v[gi];
    }
    __syncthreads();

    float ql2[4] = { q4.x, q4.y, q4.z, q4.w };

    float num[4] = {0.f, 0.f, 0.f, 0.f};
    float den[4] = {0.f, 0.f, 0.f, 0.f};

    #pragma unroll
    for (int r = 0; r < 5; r++) {
        const float4* kp = reinterpret_cast<const float4*>(&ks[(ty + r) * HSTR + wsub]);
        const float4* vp = reinterpret_cast<const float4*>(&vs[(ty + r) * HSTR + wsub]);
        float4 k0 = kp[0], k1 = kp[1];
        float4 v0 = vp[0], v1 = vp[1];
        float kk[8] = { k0.x, k0.y, k0.z, k0.w, k1.x, k1.y, k1.z, k1.w };
        float vv[8] = { v0.x, v0.y, v0.z, v0.w, v1.x, v1.y, v1.z, v1.w };
        #pragma unroll
        for (int o = 0; o < 4; o++) {
            #pragma unroll
            for (int c = 0; c < 5; c++) {
                float e = ex2(ql2[o] * kk[o + c]);
                den[o] += e;
                num[o] = fmaf(e, vv[o + c], num[o]);
            }
        }
    }

    float4 r4 = make_float4(__fdividef(num[0], den[0]),
                            __fdividef(num[1], den[1]),
                            __fdividef(num[2], den[2]),
                            __fdividef(num[3], den[3]));
    *reinterpret_cast<float4*>(&out[cbase + pix]) = r4;
}

// -----------------------------------------------------------------------------
// Launch: two kernels, single stream (the proven structure — global best).
// Inputs (metadata order): x, wq, wk, wv — all float32. Output float32.
// -----------------------------------------------------------------------------
extern "C" void kernel_launch(void* const* d_in, const int* in_sizes, int n_in,
                              void* d_out, int out_size)
{
    const float* x  = (const float*)d_in[0];
    const float* wq = (const float*)d_in[1];
    const float* wk = (const float*)d_in[2];
    const float* wv = (const float*)d_in[3];
    float* out = (float*)d_out;

    qkv_kernel<<<dim3(HHN, BB * GG), 256>>>(x, wq, wk, wv);
    attn_kernel<<<dim3(WWN / 32, HHN / 32, BB * CTOT), dim3(256)>>>(out);
}